// round 10
// baseline (speedup 1.0000x reference)
#include <cuda_runtime.h>
#include <cuda_bf16.h>
#include <math.h>
#include <stdint.h>

#define N_NODES 32768
#define E_DIM   512
#define H_HEADS 8
#define D_HEAD  64
#define NNZ_E   524288

// ---------------- scratch (static device globals; no allocations) ----------
__device__ float g_Q[(size_t)N_NODES * E_DIM];        // 64 MB
__device__ float g_K[(size_t)N_NODES * E_DIM];        // 64 MB
__device__ float g_biasT[(size_t)NNZ_E * H_HEADS];    // 16 MB, [e][h]
__device__ int   g_rowptr[N_NODES + 1];

// ---------------- prep: rowptr scatter + bias transpose (one pass) ----------
__global__ void prep_kernel(const int* __restrict__ row_index,
                            const float* __restrict__ ab) {
    int e = blockIdx.x * blockDim.x + threadIdx.x;
    if (e >= NNZ_E) return;

    // row_ptr boundary scatter (row_index is sorted)
    int r = row_index[e];
    int prev = (e == 0) ? -1 : row_index[e - 1];
    for (int rr = prev + 1; rr <= r; rr++) g_rowptr[rr] = e;
    if (e == NNZ_E - 1) {
        for (int rr = r + 1; rr <= N_NODES; rr++) g_rowptr[rr] = NNZ_E;
    }

    // att_bias transpose [H][NNZ] -> [NNZ][H]
    float4 v0, v1;
    v0.x = ab[(size_t)0 * NNZ_E + e];
    v0.y = ab[(size_t)1 * NNZ_E + e];
    v0.z = ab[(size_t)2 * NNZ_E + e];
    v0.w = ab[(size_t)3 * NNZ_E + e];
    v1.x = ab[(size_t)4 * NNZ_E + e];
    v1.y = ab[(size_t)5 * NNZ_E + e];
    v1.z = ab[(size_t)6 * NNZ_E + e];
    v1.w = ab[(size_t)7 * NNZ_E + e];
    float4* dst = (float4*)(g_biasT + (size_t)e * H_HEADS);
    dst[0] = v0; dst[1] = v1;
}

// ---------------- fused TF32 tensor-core GEMM (Q & K), 3-stage cp.async -----
// BM=BN=128, BK=32, 3-stage pipeline, 256 threads (8 warps 2x4),
// warp tile 64x32, mma.m16n8k8.tf32, pitch 36 (conflict-free).
#define GBM 128
#define GBN 128
#define GBK 32
#define KPITCH 36
#define NSTAGE 3
#define STAGE_FLOATS (GBM * KPITCH + GBN * KPITCH)       // 9216
#define GEMM_SMEM_BYTES (NSTAGE * STAGE_FLOATS * 4)       // 110592

__device__ __forceinline__ void cp_async16(uint32_t smem_addr, const void* gptr) {
    asm volatile("cp.async.cg.shared.global [%0], [%1], 16;\n"
                 :: "r"(smem_addr), "l"(gptr));
}
__device__ __forceinline__ void cp_commit() {
    asm volatile("cp.async.commit_group;\n");
}
__device__ __forceinline__ void cp_wait2() {
    asm volatile("cp.async.wait_group 2;\n");
}

__global__ __launch_bounds__(256, 2)
void gemm_tf32_fused(const float* __restrict__ A,
                     const float* __restrict__ Wq, const float* __restrict__ bq,
                     const float* __restrict__ Wk, const float* __restrict__ bk,
                     float* __restrict__ Cq, float* __restrict__ Ck)
{
    extern __shared__ float smem[];

    const int z = blockIdx.z;
    const float* W    = z ? Wk : Wq;
    const float* bias = z ? bk : bq;
    float*       C    = z ? Ck : Cq;
    const float scale = z ? 1.0f : 0.125f;   // q gets 1/sqrt(64)

    const int tid  = threadIdx.x;
    const int bm   = blockIdx.y;
    const int bn   = blockIdx.x;
    const int wid  = tid >> 5;
    const int lane = tid & 31;
    const int warp_m = wid >> 2;     // 0..1 -> 64 rows each
    const int warp_n = wid & 3;      // 0..3 -> 32 cols each
    const int g = lane >> 2;         // 0..7
    const int t = lane & 3;          // 0..3

    const int rA = tid >> 3;         // 0..31 (rows rA, rA+32, rA+64, rA+96)
    const int kc = (tid & 7) * 4;    // 0..28

    const float* Ag = A + (size_t)(bm * GBM + rA) * E_DIM + kc;
    const float* Wg = W + (size_t)(bn * GBN + rA) * E_DIM + kc;

    const uint32_t sbase = (uint32_t)__cvta_generic_to_shared(smem);
    const uint32_t aoff = (rA * KPITCH + kc) * 4;
    const uint32_t boff = (GBM * KPITCH + rA * KPITCH + kc) * 4;

    float acc[4][4][4];
    #pragma unroll
    for (int i = 0; i < 4; i++)
        #pragma unroll
        for (int j = 0; j < 4; j++)
            #pragma unroll
            for (int c = 0; c < 4; c++) acc[i][j][c] = 0.f;

    // prologue: stages 0 and 1
    #pragma unroll
    for (int st = 0; st < 2; st++) {
        const uint32_t sb = sbase + (uint32_t)st * (STAGE_FLOATS * 4);
        const int koff = st * GBK;
        #pragma unroll
        for (int j = 0; j < 4; j++) {
            cp_async16(sb + aoff + j * (32 * KPITCH * 4),
                       Ag + koff + (size_t)j * 32 * E_DIM);
            cp_async16(sb + boff + j * (32 * KPITCH * 4),
                       Wg + koff + (size_t)j * 32 * E_DIM);
        }
        cp_commit();
    }

    const int NIT = E_DIM / GBK;     // 16

    for (int it = 0; it < NIT; it++) {
        const int pf = it + 2;
        if (pf < NIT) {
            const int koff = pf * GBK;
            const uint32_t sb = sbase + (uint32_t)(pf % NSTAGE) * (STAGE_FLOATS * 4);
            #pragma unroll
            for (int j = 0; j < 4; j++) {
                cp_async16(sb + aoff + j * (32 * KPITCH * 4),
                           Ag + koff + (size_t)j * 32 * E_DIM);
                cp_async16(sb + boff + j * (32 * KPITCH * 4),
                           Wg + koff + (size_t)j * 32 * E_DIM);
            }
        }
        cp_commit();
        cp_wait2();            // all but 2 newest groups done -> stage `it` ready
        __syncthreads();

        const float* __restrict__ Ac = smem + (it % NSTAGE) * STAGE_FLOATS;
        const float* __restrict__ Bc = Ac + GBM * KPITCH;

        #pragma unroll
        for (int ks = 0; ks < 4; ks++) {
            const int kb = ks * 8;
            uint32_t af[4][4], bf[4][2];
            #pragma unroll
            for (int i = 0; i < 4; i++) {
                int m = warp_m * 64 + i * 16;
                af[i][0] = __float_as_uint(Ac[(m + g    ) * KPITCH + kb + t    ]);
                af[i][1] = __float_as_uint(Ac[(m + g + 8) * KPITCH + kb + t    ]);
                af[i][2] = __float_as_uint(Ac[(m + g    ) * KPITCH + kb + t + 4]);
                af[i][3] = __float_as_uint(Ac[(m + g + 8) * KPITCH + kb + t + 4]);
            }
            #pragma unroll
            for (int j = 0; j < 4; j++) {
                int n = warp_n * 32 + j * 8;
                bf[j][0] = __float_as_uint(Bc[(n + g) * KPITCH + kb + t    ]);
                bf[j][1] = __float_as_uint(Bc[(n + g) * KPITCH + kb + t + 4]);
            }
            #pragma unroll
            for (int i = 0; i < 4; i++)
                #pragma unroll
                for (int j = 0; j < 4; j++) {
                    asm volatile(
                        "mma.sync.aligned.m16n8k8.row.col.f32.tf32.tf32.f32 "
                        "{%0,%1,%2,%3}, {%4,%5,%6,%7}, {%8,%9}, {%0,%1,%2,%3};"
                        : "+f"(acc[i][j][0]), "+f"(acc[i][j][1]),
                          "+f"(acc[i][j][2]), "+f"(acc[i][j][3])
                        : "r"(af[i][0]), "r"(af[i][1]), "r"(af[i][2]), "r"(af[i][3]),
                          "r"(bf[j][0]), "r"(bf[j][1]));
                }
        }
        __syncthreads();
    }

    const int mbase = bm * GBM + warp_m * 64;
    const int nbase = bn * GBN + warp_n * 32;
    #pragma unroll
    for (int i = 0; i < 4; i++) {
        #pragma unroll
        for (int j = 0; j < 4; j++) {
            int row0e = mbase + i * 16 + g;
            int col   = nbase + j * 8 + t * 2;
            float b0 = bias[col], b1 = bias[col + 1];
            float2 o0, o1;
            o0.x = (acc[i][j][0] + b0) * scale;
            o0.y = (acc[i][j][1] + b1) * scale;
            o1.x = (acc[i][j][2] + b0) * scale;
            o1.y = (acc[i][j][3] + b1) * scale;
            *(float2*)(C + (size_t)row0e * E_DIM + col)       = o0;
            *(float2*)(C + (size_t)(row0e + 8) * E_DIM + col) = o1;
        }
    }
}

// ---------------- fused edge logits + softmax + output ----------------------
// TWO warps per row: warp pair (2p, 2p+1) splits the row's edge range in half;
// partial states (pure sums, no running max) merge by addition via smem.
// Within a warp: lane l holds Q floats [l*16,l*16+16); 2 edges/iteration.
__global__ __launch_bounds__(256)
void fused_attn_kernel(const int* __restrict__ col_index,
                       const int* __restrict__ to_col_index,
                       const float* __restrict__ dist,
                       const float* __restrict__ pos,
                       const float* __restrict__ col_pos,
                       float* __restrict__ out)
{
    __shared__ float part[8][40];   // [warp][head*5 + {z,s0,vx,vy,vz}]

    const int tidx = threadIdx.x;
    const int wid  = tidx >> 5;
    const int lane = tidx & 31;
    const int r    = blockIdx.x * 4 + (wid >> 1);
    const int half = wid & 1;

    const int s  = g_rowptr[r];
    const int e1 = g_rowptr[r + 1];
    const int mid = s + ((e1 - s + 1) >> 1);
    const int lo = half ? mid : s;
    const int hi = half ? e1 : mid;

    float4 q0, q1, q2, q3;
    {
        const float4* qp = (const float4*)(g_Q + (size_t)r * E_DIM + lane * 16);
        q0 = qp[0]; q1 = qp[1]; q2 = qp[2]; q3 = qp[3];
    }

    // two independent state sets (valid on lanes 0..7, head == lane)
    float zA = 0.f, sA = 0.f, vxA = 0.f, vyA = 0.f, vzA = 0.f;
    float zB = 0.f, sB = 0.f, vxB = 0.f, vyB = 0.f, vzB = 0.f;
    const int bsrc = (lane * 4) & 31;   // shfl source for head==lane

    for (int base = lo; base < hi; base += 32) {
        int myE = base + lane;
        int tc = 0; float dd = 0.f, cxl = 0.f, cyl = 0.f, czl = 0.f;
        if (myE < hi) {
            int c = col_index[myE];
            tc = to_col_index[c];
            dd = dist[myE];
            cxl = col_pos[(size_t)c * 3 + 0];
            cyl = col_pos[(size_t)c * 3 + 1];
            czl = col_pos[(size_t)c * 3 + 2];
        }
        int cnt = min(32, hi - base);

        int i = 0;
        for (; i + 2 <= cnt; i += 2) {
            int t0 = __shfl_sync(0xFFFFFFFFu, tc, i);
            int t1 = __shfl_sync(0xFFFFFFFFu, tc, i + 1);
            const float4* kpa = (const float4*)(g_K + (size_t)t0 * E_DIM + lane * 16);
            const float4* kpb = (const float4*)(g_K + (size_t)t1 * E_DIM + lane * 16);
            float4 a0 = kpa[0], a1 = kpa[1], a2 = kpa[2], a3 = kpa[3];
            float4 b0 = kpb[0], b1 = kpb[1], b2 = kpb[2], b3 = kpb[3];

            float d0 = q0.x * a0.x, d1 = q0.x * b0.x;
            d0 = fmaf(q0.y, a0.y, d0); d1 = fmaf(q0.y, b0.y, d1);
            d0 = fmaf(q0.z, a0.z, d0); d1 = fmaf(q0.z, b0.z, d1);
            d0 = fmaf(q0.w, a0.w, d0); d1 = fmaf(q0.w, b0.w, d1);
            d0 = fmaf(q1.x, a1.x, d0); d1 = fmaf(q1.x, b1.x, d1);
            d0 = fmaf(q1.y, a1.y, d0); d1 = fmaf(q1.y, b1.y, d1);
            d0 = fmaf(q1.z, a1.z, d0); d1 = fmaf(q1.z, b1.z, d1);
            d0 = fmaf(q1.w, a1.w, d0); d1 = fmaf(q1.w, b1.w, d1);
            d0 = fmaf(q2.x, a2.x, d0); d1 = fmaf(q2.x, b2.x, d1);
            d0 = fmaf(q2.y, a2.y, d0); d1 = fmaf(q2.y, b2.y, d1);
            d0 = fmaf(q2.z, a2.z, d0); d1 = fmaf(q2.z, b2.z, d1);
            d0 = fmaf(q2.w, a2.w, d0); d1 = fmaf(q2.w, b2.w, d1);
            d0 = fmaf(q3.x, a3.x, d0); d1 = fmaf(q3.x, b3.x, d1);
            d0 = fmaf(q3.y, a3.y, d0); d1 = fmaf(q3.y, b3.y, d1);
            d0 = fmaf(q3.z, a3.z, d0); d1 = fmaf(q3.z, b3.z, d1);
            d0 = fmaf(q3.w, a3.w, d0); d1 = fmaf(q3.w, b3.w, d1);

            d0 += __shfl_xor_sync(0xFFFFFFFFu, d0, 1);
            d1 += __shfl_xor_sync(0xFFFFFFFFu, d1, 1);
            d0 += __shfl_xor_sync(0xFFFFFFFFu, d0, 2);
            d1 += __shfl_xor_sync(0xFFFFFFFFu, d1, 2);

            float hv0 = __shfl_sync(0xFFFFFFFFu, d0, bsrc);
            float hv1 = __shfl_sync(0xFFFFFFFFu, d1, bsrc);
            float dd0 = __shfl_sync(0xFFFFFFFFu, dd,  i);
            float dd1 = __shfl_sync(0xFFFFFFFFu, dd,  i + 1);
            float cx0 = __shfl_sync(0xFFFFFFFFu, cxl, i);
            float cx1 = __shfl_sync(0xFFFFFFFFu, cxl, i + 1);
            float cy0 = __shfl_sync(0xFFFFFFFFu, cyl, i);
            float cy1 = __shfl_sync(0xFFFFFFFFu, cyl, i + 1);
            float cz0 = __shfl_sync(0xFFFFFFFFu, czl, i);
            float cz1 = __shfl_sync(0xFFFFFFFFu, czl, i + 1);

            if (lane < H_HEADS) {
                float lg0 = hv0 + g_biasT[(size_t)(base + i)     * H_HEADS + lane];
                float lg1 = hv1 + g_biasT[(size_t)(base + i + 1) * H_HEADS + lane];
                float p0 = __expf(lg0),            p1 = __expf(lg1);
                float i0 = (dd0 == 0.f) ? 0.f : (1.f / dd0);
                float i1 = (dd1 == 0.f) ? 0.f : (1.f / dd1);
                float w0 = p0 * i0,                w1 = p1 * i1;
                zA += p0;  zB += p1;
                sA += w0;  sB += w1;
                vxA = fmaf(w0, cx0, vxA);  vxB = fmaf(w1, cx1, vxB);
                vyA = fmaf(w0, cy0, vyA);  vyB = fmaf(w1, cy1, vyB);
                vzA = fmaf(w0, cz0, vzA);  vzB = fmaf(w1, cz1, vzB);
            }
        }
        if (i < cnt) {
            int t0 = __shfl_sync(0xFFFFFFFFu, tc, i);
            const float4* kpa = (const float4*)(g_K + (size_t)t0 * E_DIM + lane * 16);
            float4 a0 = kpa[0], a1 = kpa[1], a2 = kpa[2], a3 = kpa[3];
            float d0 = q0.x * a0.x;
            d0 = fmaf(q0.y, a0.y, d0); d0 = fmaf(q0.z, a0.z, d0); d0 = fmaf(q0.w, a0.w, d0);
            d0 = fmaf(q1.x, a1.x, d0); d0 = fmaf(q1.y, a1.y, d0);
            d0 = fmaf(q1.z, a1.z, d0); d0 = fmaf(q1.w, a1.w, d0);
            d0 = fmaf(q2.x, a2.x, d0); d0 = fmaf(q2.y, a2.y, d0);
            d0 = fmaf(q2.z, a2.z, d0); d0 = fmaf(q2.w, a2.w, d0);
            d0 = fmaf(q3.x, a3.x, d0); d0 = fmaf(q3.y, a3.y, d0);
            d0 = fmaf(q3.z, a3.z, d0); d0 = fmaf(q3.w, a3.w, d0);
            d0 += __shfl_xor_sync(0xFFFFFFFFu, d0, 1);
            d0 += __shfl_xor_sync(0xFFFFFFFFu, d0, 2);
            float hv0 = __shfl_sync(0xFFFFFFFFu, d0, bsrc);
            float dd0 = __shfl_sync(0xFFFFFFFFu, dd,  i);
            float cx0 = __shfl_sync(0xFFFFFFFFu, cxl, i);
            float cy0 = __shfl_sync(0xFFFFFFFFu, cyl, i);
            float cz0 = __shfl_sync(0xFFFFFFFFu, czl, i);
            if (lane < H_HEADS) {
                float lg0 = hv0 + g_biasT[(size_t)(base + i) * H_HEADS + lane];
                float p0 = __expf(lg0);
                float i0 = (dd0 == 0.f) ? 0.f : (1.f / dd0);
                float w0 = p0 * i0;
                zA += p0; sA += w0;
                vxA = fmaf(w0, cx0, vxA);
                vyA = fmaf(w0, cy0, vyA);
                vzA = fmaf(w0, cz0, vzA);
            }
        }
    }

    // publish partial state
    if (lane < H_HEADS) {
        float* p = &part[wid][lane * 5];
        p[0] = zA + zB;
        p[1] = sA + sB;
        p[2] = vxA + vxB;
        p[3] = vyA + vyB;
        p[4] = vzA + vzB;
    }
    __syncthreads();

    // even warp of each pair combines and finalizes
    if (half == 0 && lane < H_HEADS) {
        const float* mine = &part[wid][lane * 5];
        const float* othr = &part[wid + 1][lane * 5];
        float z  = mine[0] + othr[0];
        float s0 = mine[1] + othr[1];
        float vx = mine[2] + othr[2];
        float vy = mine[3] + othr[3];
        float vz = mine[4] + othr[4];
        float4 o = make_float4(0.f, 0.f, 0.f, 0.f);
        if (z > 0.f) {
            float invZ = 1.f / z;
            float avg = s0 * invZ;
            float px = pos[(size_t)r * 3 + 0];
            float py = pos[(size_t)r * 3 + 1];
            float pz = pos[(size_t)r * 3 + 2];
            float dx = vx * invZ - avg * px;
            float dy = vy * invZ - avg * py;
            float dz = vz * invZ - avg * pz;
            float nm = sqrtf(dx * dx + dy * dy + dz * dz);
            float dnm = fmaxf(nm, 1e-12f);
            o.x = dx / dnm; o.y = dy / dnm; o.z = dz / dnm; o.w = avg;
        }
        *(float4*)(out + (size_t)r * (H_HEADS * 4) + lane * 4) = o;
    }
}

// ---------------- launch ----------------------------------------------------
extern "C" void kernel_launch(void* const* d_in, const int* in_sizes, int n_in,
                              void* d_out, int out_size)
{
    const float* x            = (const float*)d_in[0];
    const int*   row_index    = (const int*)  d_in[1];
    const int*   col_index    = (const int*)  d_in[2];
    const int*   to_col_index = (const int*)  d_in[3];
    const float* att_bias     = (const float*)d_in[4];
    const float* dist         = (const float*)d_in[5];
    const float* pos          = (const float*)d_in[6];
    const float* col_pos      = (const float*)d_in[7];
    const float* q_w          = (const float*)d_in[8];
    const float* q_b          = (const float*)d_in[9];
    const float* k_w          = (const float*)d_in[10];
    const float* k_b          = (const float*)d_in[11];
    float* out = (float*)d_out;

    float* Qg; cudaGetSymbolAddress((void**)&Qg, g_Q);
    float* Kg; cudaGetSymbolAddress((void**)&Kg, g_K);

    prep_kernel<<<NNZ_E / 256, 256>>>(row_index, att_bias);

    cudaFuncSetAttribute(gemm_tf32_fused,
                         cudaFuncAttributeMaxDynamicSharedMemorySize,
                         GEMM_SMEM_BYTES);
    dim3 ggrid(E_DIM / GBN, N_NODES / GBM, 2);
    gemm_tf32_fused<<<ggrid, 256, GEMM_SMEM_BYTES>>>(x, q_w, q_b, k_w, k_b, Qg, Kg);

    fused_attn_kernel<<<N_NODES / 4, 256>>>(col_index, to_col_index,
                                            dist, pos, col_pos, out);
}

// round 11
// speedup vs baseline: 1.6538x; 1.6538x over previous
#include <cuda_runtime.h>
#include <cuda_bf16.h>
#include <math.h>
#include <stdint.h>

#define N_NODES 32768
#define E_DIM   512
#define H_HEADS 8
#define D_HEAD  64
#define NNZ_E   524288

// ---------------- scratch (static device globals; no allocations) ----------
__device__ float  g_Q[(size_t)N_NODES * E_DIM];        // 64 MB
__device__ float  g_K[(size_t)N_NODES * E_DIM];        // 64 MB
__device__ float  g_biasT[(size_t)NNZ_E * H_HEADS];    // 16 MB, [e][h]
__device__ float4 g_edata[NNZ_E];                      // 8 MB {cx,cy,cz,inv_d}
__device__ int    g_tcol[NNZ_E];                       // 2 MB to_col[col[e]]
__device__ int    g_rowptr[N_NODES + 1];

// ---------------- prep: rowptr + biasT + per-edge gather --------------------
__global__ void prep_kernel(const int* __restrict__ row_index,
                            const float* __restrict__ ab,
                            const int* __restrict__ col_index,
                            const int* __restrict__ to_col_index,
                            const float* __restrict__ dist,
                            const float* __restrict__ col_pos) {
    int e = blockIdx.x * blockDim.x + threadIdx.x;
    if (e >= NNZ_E) return;

    // row_ptr boundary scatter (row_index is sorted)
    int r = row_index[e];
    int prev = (e == 0) ? -1 : row_index[e - 1];
    for (int rr = prev + 1; rr <= r; rr++) g_rowptr[rr] = e;
    if (e == NNZ_E - 1) {
        for (int rr = r + 1; rr <= N_NODES; rr++) g_rowptr[rr] = NNZ_E;
    }

    // att_bias transpose [H][NNZ] -> [NNZ][H]
    float4 v0, v1;
    v0.x = ab[(size_t)0 * NNZ_E + e];
    v0.y = ab[(size_t)1 * NNZ_E + e];
    v0.z = ab[(size_t)2 * NNZ_E + e];
    v0.w = ab[(size_t)3 * NNZ_E + e];
    v1.x = ab[(size_t)4 * NNZ_E + e];
    v1.y = ab[(size_t)5 * NNZ_E + e];
    v1.z = ab[(size_t)6 * NNZ_E + e];
    v1.w = ab[(size_t)7 * NNZ_E + e];
    float4* dst = (float4*)(g_biasT + (size_t)e * H_HEADS);
    dst[0] = v0; dst[1] = v1;

    // per-edge gathered data
    int c = col_index[e];
    g_tcol[e] = to_col_index[c];
    float dd = dist[e];
    float inv = (dd == 0.f) ? 0.f : (1.f / dd);
    float4 ed;
    ed.x = col_pos[(size_t)c * 3 + 0];
    ed.y = col_pos[(size_t)c * 3 + 1];
    ed.z = col_pos[(size_t)c * 3 + 2];
    ed.w = inv;
    g_edata[e] = ed;
}

// ---------------- fused TF32 tensor-core GEMM (Q & K), 2-stage cp.async -----
// BM=BN=128, BK=32, 2-stage (73.7 KB smem -> 2 CTA/SM), 256 threads (2x4
// warps), warp tile 64x32, mma.m16n8k8.tf32, pitch 36 (conflict-free).
#define GBM 128
#define GBN 128
#define GBK 32
#define KPITCH 36
#define STAGE_FLOATS (GBM * KPITCH + GBN * KPITCH)   // 9216
#define GEMM_SMEM_BYTES (2 * STAGE_FLOATS * 4)        // 73728

__device__ __forceinline__ void cp_async16(uint32_t smem_addr, const void* gptr) {
    asm volatile("cp.async.cg.shared.global [%0], [%1], 16;\n"
                 :: "r"(smem_addr), "l"(gptr));
}
__device__ __forceinline__ void cp_commit() {
    asm volatile("cp.async.commit_group;\n");
}
__device__ __forceinline__ void cp_wait1() {
    asm volatile("cp.async.wait_group 1;\n");
}

__global__ __launch_bounds__(256, 2)
void gemm_tf32_fused(const float* __restrict__ A,
                     const float* __restrict__ Wq, const float* __restrict__ bq,
                     const float* __restrict__ Wk, const float* __restrict__ bk,
                     float* __restrict__ Cq, float* __restrict__ Ck)
{
    extern __shared__ float smem[];

    const int z = blockIdx.z;
    const float* W    = z ? Wk : Wq;
    const float* bias = z ? bk : bq;
    float*       C    = z ? Ck : Cq;
    const float scale = z ? 1.0f : 0.125f;   // q gets 1/sqrt(64)

    const int tid  = threadIdx.x;
    const int bm   = blockIdx.y;
    const int bn   = blockIdx.x;
    const int wid  = tid >> 5;
    const int lane = tid & 31;
    const int warp_m = wid >> 2;     // 0..1 -> 64 rows each
    const int warp_n = wid & 3;      // 0..3 -> 32 cols each
    const int g = lane >> 2;         // 0..7
    const int t = lane & 3;          // 0..3

    const int rA = tid >> 3;         // 0..31 (rows rA, rA+32, rA+64, rA+96)
    const int kc = (tid & 7) * 4;    // 0..28

    const float* Ag = A + (size_t)(bm * GBM + rA) * E_DIM + kc;
    const float* Wg = W + (size_t)(bn * GBN + rA) * E_DIM + kc;

    const uint32_t sbase = (uint32_t)__cvta_generic_to_shared(smem);
    const uint32_t aoff = (rA * KPITCH + kc) * 4;
    const uint32_t boff = (GBM * KPITCH + rA * KPITCH + kc) * 4;

    float acc[4][4][4];
    #pragma unroll
    for (int i = 0; i < 4; i++)
        #pragma unroll
        for (int j = 0; j < 4; j++)
            #pragma unroll
            for (int c = 0; c < 4; c++) acc[i][j][c] = 0.f;

    {
        const uint32_t sb = sbase;
        #pragma unroll
        for (int j = 0; j < 4; j++) {
            cp_async16(sb + aoff + j * (32 * KPITCH * 4), Ag + (size_t)j * 32 * E_DIM);
            cp_async16(sb + boff + j * (32 * KPITCH * 4), Wg + (size_t)j * 32 * E_DIM);
        }
    }
    cp_commit();

    const int NIT = E_DIM / GBK;     // 16
    int cur = 0;

    for (int it = 0; it < NIT; it++) {
        if (it + 1 < NIT) {
            const int koff = (it + 1) * GBK;
            const uint32_t sb = sbase + (uint32_t)(cur ^ 1) * (STAGE_FLOATS * 4);
            #pragma unroll
            for (int j = 0; j < 4; j++) {
                cp_async16(sb + aoff + j * (32 * KPITCH * 4),
                           Ag + koff + (size_t)j * 32 * E_DIM);
                cp_async16(sb + boff + j * (32 * KPITCH * 4),
                           Wg + koff + (size_t)j * 32 * E_DIM);
            }
        }
        cp_commit();
        cp_wait1();
        __syncthreads();

        const float* __restrict__ Ac = smem + cur * STAGE_FLOATS;
        const float* __restrict__ Bc = Ac + GBM * KPITCH;

        #pragma unroll
        for (int ks = 0; ks < 4; ks++) {
            const int kb = ks * 8;
            uint32_t af[4][4], bf[4][2];
            #pragma unroll
            for (int i = 0; i < 4; i++) {
                int m = warp_m * 64 + i * 16;
                af[i][0] = __float_as_uint(Ac[(m + g    ) * KPITCH + kb + t    ]);
                af[i][1] = __float_as_uint(Ac[(m + g + 8) * KPITCH + kb + t    ]);
                af[i][2] = __float_as_uint(Ac[(m + g    ) * KPITCH + kb + t + 4]);
                af[i][3] = __float_as_uint(Ac[(m + g + 8) * KPITCH + kb + t + 4]);
            }
            #pragma unroll
            for (int j = 0; j < 4; j++) {
                int n = warp_n * 32 + j * 8;
                bf[j][0] = __float_as_uint(Bc[(n + g) * KPITCH + kb + t    ]);
                bf[j][1] = __float_as_uint(Bc[(n + g) * KPITCH + kb + t + 4]);
            }
            #pragma unroll
            for (int i = 0; i < 4; i++)
                #pragma unroll
                for (int j = 0; j < 4; j++) {
                    asm volatile(
                        "mma.sync.aligned.m16n8k8.row.col.f32.tf32.tf32.f32 "
                        "{%0,%1,%2,%3}, {%4,%5,%6,%7}, {%8,%9}, {%0,%1,%2,%3};"
                        : "+f"(acc[i][j][0]), "+f"(acc[i][j][1]),
                          "+f"(acc[i][j][2]), "+f"(acc[i][j][3])
                        : "r"(af[i][0]), "r"(af[i][1]), "r"(af[i][2]), "r"(af[i][3]),
                          "r"(bf[j][0]), "r"(bf[j][1]));
                }
        }
        __syncthreads();
        cur ^= 1;
    }

    const int mbase = bm * GBM + warp_m * 64;
    const int nbase = bn * GBN + warp_n * 32;
    #pragma unroll
    for (int i = 0; i < 4; i++) {
        #pragma unroll
        for (int j = 0; j < 4; j++) {
            int row0e = mbase + i * 16 + g;
            int col   = nbase + j * 8 + t * 2;
            float b0 = bias[col], b1 = bias[col + 1];
            float2 o0, o1;
            o0.x = (acc[i][j][0] + b0) * scale;
            o0.y = (acc[i][j][1] + b1) * scale;
            o1.x = (acc[i][j][2] + b0) * scale;
            o1.y = (acc[i][j][3] + b1) * scale;
            *(float2*)(C + (size_t)row0e * E_DIM + col)       = o0;
            *(float2*)(C + (size_t)(row0e + 8) * E_DIM + col) = o1;
        }
    }
}

// ---------------- fused edge logits + softmax + output ----------------------
// One warp per row; lane l holds Q floats [l*16,l*16+16); 2 edges/iteration;
// no max-subtraction (shift-invariant softmax, small logits). Per-edge data
// comes from the precomputed g_edata/g_tcol (broadcast float4 reads on lanes
// 0..7 instead of gathers + shfl broadcasts).
__global__ __launch_bounds__(256)
void fused_attn_kernel(const float* __restrict__ pos,
                       float* __restrict__ out)
{
    int r = (blockIdx.x * blockDim.x + threadIdx.x) >> 5;
    if (r >= N_NODES) return;
    const int lane = threadIdx.x & 31;

    const int s  = g_rowptr[r];
    const int e1 = g_rowptr[r + 1];

    if (s == e1) {
        if (lane < H_HEADS)
            *(float4*)(out + (size_t)r * (H_HEADS * 4) + lane * 4) =
                make_float4(0.f, 0.f, 0.f, 0.f);
        return;
    }

    float4 q0, q1, q2, q3;
    {
        const float4* qp = (const float4*)(g_Q + (size_t)r * E_DIM + lane * 16);
        q0 = qp[0]; q1 = qp[1]; q2 = qp[2]; q3 = qp[3];
    }

    // two independent state sets (valid on lanes 0..7, head == lane)
    float zA = 0.f, sA = 0.f, vxA = 0.f, vyA = 0.f, vzA = 0.f;
    float zB = 0.f, sB = 0.f, vxB = 0.f, vyB = 0.f, vzB = 0.f;
    const int bsrc = (lane * 4) & 31;   // shfl source for head==lane

    for (int base = s; base < e1; base += 32) {
        int myE = base + lane;
        int tc = (myE < e1) ? g_tcol[myE] : 0;
        int cnt = min(32, e1 - base);

        int i = 0;
        for (; i + 2 <= cnt; i += 2) {
            int t0 = __shfl_sync(0xFFFFFFFFu, tc, i);
            int t1 = __shfl_sync(0xFFFFFFFFu, tc, i + 1);
            const float4* kpa = (const float4*)(g_K + (size_t)t0 * E_DIM + lane * 16);
            const float4* kpb = (const float4*)(g_K + (size_t)t1 * E_DIM + lane * 16);
            float4 a0 = kpa[0], a1 = kpa[1], a2 = kpa[2], a3 = kpa[3];
            float4 b0 = kpb[0], b1 = kpb[1], b2 = kpb[2], b3 = kpb[3];

            float d0 = q0.x * a0.x, d1 = q0.x * b0.x;
            d0 = fmaf(q0.y, a0.y, d0); d1 = fmaf(q0.y, b0.y, d1);
            d0 = fmaf(q0.z, a0.z, d0); d1 = fmaf(q0.z, b0.z, d1);
            d0 = fmaf(q0.w, a0.w, d0); d1 = fmaf(q0.w, b0.w, d1);
            d0 = fmaf(q1.x, a1.x, d0); d1 = fmaf(q1.x, b1.x, d1);
            d0 = fmaf(q1.y, a1.y, d0); d1 = fmaf(q1.y, b1.y, d1);
            d0 = fmaf(q1.z, a1.z, d0); d1 = fmaf(q1.z, b1.z, d1);
            d0 = fmaf(q1.w, a1.w, d0); d1 = fmaf(q1.w, b1.w, d1);
            d0 = fmaf(q2.x, a2.x, d0); d1 = fmaf(q2.x, b2.x, d1);
            d0 = fmaf(q2.y, a2.y, d0); d1 = fmaf(q2.y, b2.y, d1);
            d0 = fmaf(q2.z, a2.z, d0); d1 = fmaf(q2.z, b2.z, d1);
            d0 = fmaf(q2.w, a2.w, d0); d1 = fmaf(q2.w, b2.w, d1);
            d0 = fmaf(q3.x, a3.x, d0); d1 = fmaf(q3.x, b3.x, d1);
            d0 = fmaf(q3.y, a3.y, d0); d1 = fmaf(q3.y, b3.y, d1);
            d0 = fmaf(q3.z, a3.z, d0); d1 = fmaf(q3.z, b3.z, d1);
            d0 = fmaf(q3.w, a3.w, d0); d1 = fmaf(q3.w, b3.w, d1);

            d0 += __shfl_xor_sync(0xFFFFFFFFu, d0, 1);
            d1 += __shfl_xor_sync(0xFFFFFFFFu, d1, 1);
            d0 += __shfl_xor_sync(0xFFFFFFFFu, d0, 2);
            d1 += __shfl_xor_sync(0xFFFFFFFFu, d1, 2);

            float hv0 = __shfl_sync(0xFFFFFFFFu, d0, bsrc);
            float hv1 = __shfl_sync(0xFFFFFFFFu, d1, bsrc);

            if (lane < H_HEADS) {
                float4 ed0 = g_edata[base + i];
                float4 ed1 = g_edata[base + i + 1];
                float lg0 = hv0 + g_biasT[(size_t)(base + i)     * H_HEADS + lane];
                float lg1 = hv1 + g_biasT[(size_t)(base + i + 1) * H_HEADS + lane];
                float p0 = __expf(lg0), p1 = __expf(lg1);
                float w0 = p0 * ed0.w, w1 = p1 * ed1.w;
                zA += p0;  zB += p1;
                sA += w0;  sB += w1;
                vxA = fmaf(w0, ed0.x, vxA);  vxB = fmaf(w1, ed1.x, vxB);
                vyA = fmaf(w0, ed0.y, vyA);  vyB = fmaf(w1, ed1.y, vyB);
                vzA = fmaf(w0, ed0.z, vzA);  vzB = fmaf(w1, ed1.z, vzB);
            }
        }
        if (i < cnt) {
            int t0 = __shfl_sync(0xFFFFFFFFu, tc, i);
            const float4* kpa = (const float4*)(g_K + (size_t)t0 * E_DIM + lane * 16);
            float4 a0 = kpa[0], a1 = kpa[1], a2 = kpa[2], a3 = kpa[3];
            float d0 = q0.x * a0.x;
            d0 = fmaf(q0.y, a0.y, d0); d0 = fmaf(q0.z, a0.z, d0); d0 = fmaf(q0.w, a0.w, d0);
            d0 = fmaf(q1.x, a1.x, d0); d0 = fmaf(q1.y, a1.y, d0);
            d0 = fmaf(q1.z, a1.z, d0); d0 = fmaf(q1.w, a1.w, d0);
            d0 = fmaf(q2.x, a2.x, d0); d0 = fmaf(q2.y, a2.y, d0);
            d0 = fmaf(q2.z, a2.z, d0); d0 = fmaf(q2.w, a2.w, d0);
            d0 = fmaf(q3.x, a3.x, d0); d0 = fmaf(q3.y, a3.y, d0);
            d0 = fmaf(q3.z, a3.z, d0); d0 = fmaf(q3.w, a3.w, d0);
            d0 += __shfl_xor_sync(0xFFFFFFFFu, d0, 1);
            d0 += __shfl_xor_sync(0xFFFFFFFFu, d0, 2);
            float hv0 = __shfl_sync(0xFFFFFFFFu, d0, bsrc);
            if (lane < H_HEADS) {
                float4 ed0 = g_edata[base + i];
                float lg0 = hv0 + g_biasT[(size_t)(base + i) * H_HEADS + lane];
                float p0 = __expf(lg0);
                float w0 = p0 * ed0.w;
                zA += p0; sA += w0;
                vxA = fmaf(w0, ed0.x, vxA);
                vyA = fmaf(w0, ed0.y, vyA);
                vzA = fmaf(w0, ed0.z, vzA);
            }
        }
    }

    if (lane < H_HEADS) {
        float z  = zA + zB;
        float s0 = sA + sB;
        float vx = vxA + vxB, vy = vyA + vyB, vz = vzA + vzB;
        float4 o = make_float4(0.f, 0.f, 0.f, 0.f);
        if (z > 0.f) {
            float invZ = 1.f / z;
            float avg = s0 * invZ;
            float px = pos[(size_t)r * 3 + 0];
            float py = pos[(size_t)r * 3 + 1];
            float pz = pos[(size_t)r * 3 + 2];
            float dx = vx * invZ - avg * px;
            float dy = vy * invZ - avg * py;
            float dz = vz * invZ - avg * pz;
            float nm = sqrtf(dx * dx + dy * dy + dz * dz);
            float dnm = fmaxf(nm, 1e-12f);
            o.x = dx / dnm; o.y = dy / dnm; o.z = dz / dnm; o.w = avg;
        }
        *(float4*)(out + (size_t)r * (H_HEADS * 4) + lane * 4) = o;
    }
}

// ---------------- launch ----------------------------------------------------
extern "C" void kernel_launch(void* const* d_in, const int* in_sizes, int n_in,
                              void* d_out, int out_size)
{
    const float* x            = (const float*)d_in[0];
    const int*   row_index    = (const int*)  d_in[1];
    const int*   col_index    = (const int*)  d_in[2];
    const int*   to_col_index = (const int*)  d_in[3];
    const float* att_bias     = (const float*)d_in[4];
    const float* dist         = (const float*)d_in[5];
    const float* pos          = (const float*)d_in[6];
    const float* col_pos      = (const float*)d_in[7];
    const float* q_w          = (const float*)d_in[8];
    const float* q_b          = (const float*)d_in[9];
    const float* k_w          = (const float*)d_in[10];
    const float* k_b          = (const float*)d_in[11];
    float* out = (float*)d_out;

    float* Qg; cudaGetSymbolAddress((void**)&Qg, g_Q);
    float* Kg; cudaGetSymbolAddress((void**)&Kg, g_K);

    prep_kernel<<<NNZ_E / 256, 256>>>(row_index, att_bias, col_index,
                                      to_col_index, dist, col_pos);

    cudaFuncSetAttribute(gemm_tf32_fused,
                         cudaFuncAttributeMaxDynamicSharedMemorySize,
                         GEMM_SMEM_BYTES);
    dim3 ggrid(E_DIM / GBN, N_NODES / GBM, 2);
    gemm_tf32_fused<<<ggrid, 256, GEMM_SMEM_BYTES>>>(x, q_w, q_b, k_w, k_b, Qg, Kg);

    fused_attn_kernel<<<N_NODES / 8, 256>>>(pos, out);
}

// round 13
// speedup vs baseline: 1.6774x; 1.0143x over previous
#include <cuda_runtime.h>
#include <cuda_bf16.h>
#include <math.h>
#include <stdint.h>

#define N_NODES 32768
#define E_DIM   512
#define H_HEADS 8
#define D_HEAD  64
#define NNZ_E   524288

// ---------------- scratch (static device globals; no allocations) ----------
__device__ float  g_Q[(size_t)N_NODES * E_DIM];        // 64 MB
__device__ float  g_K[(size_t)N_NODES * E_DIM];        // 64 MB
__device__ float  g_biasT[(size_t)NNZ_E * H_HEADS];    // 16 MB, [e][h]
__device__ float4 g_edata[NNZ_E];                      // 8 MB {cx,cy,cz,inv_d}
__device__ int    g_tcol[NNZ_E];                       // 2 MB to_col[col[e]]
__device__ int    g_rowptr[N_NODES + 1];

// ---------------- prep: rowptr + biasT + per-edge gather --------------------
__global__ void prep_kernel(const int* __restrict__ row_index,
                            const float* __restrict__ ab,
                            const int* __restrict__ col_index,
                            const int* __restrict__ to_col_index,
                            const float* __restrict__ dist,
                            const float* __restrict__ col_pos) {
    int e = blockIdx.x * blockDim.x + threadIdx.x;
    if (e >= NNZ_E) return;

    // row_ptr boundary scatter (row_index is sorted)
    int r = row_index[e];
    int prev = (e == 0) ? -1 : row_index[e - 1];
    for (int rr = prev + 1; rr <= r; rr++) g_rowptr[rr] = e;
    if (e == NNZ_E - 1) {
        for (int rr = r + 1; rr <= N_NODES; rr++) g_rowptr[rr] = NNZ_E;
    }

    // att_bias transpose [H][NNZ] -> [NNZ][H]
    float4 v0, v1;
    v0.x = ab[(size_t)0 * NNZ_E + e];
    v0.y = ab[(size_t)1 * NNZ_E + e];
    v0.z = ab[(size_t)2 * NNZ_E + e];
    v0.w = ab[(size_t)3 * NNZ_E + e];
    v1.x = ab[(size_t)4 * NNZ_E + e];
    v1.y = ab[(size_t)5 * NNZ_E + e];
    v1.z = ab[(size_t)6 * NNZ_E + e];
    v1.w = ab[(size_t)7 * NNZ_E + e];
    float4* dst = (float4*)(g_biasT + (size_t)e * H_HEADS);
    dst[0] = v0; dst[1] = v1;

    // per-edge gathered data
    int c = col_index[e];
    g_tcol[e] = to_col_index[c];
    float dd = dist[e];
    float inv = (dd == 0.f) ? 0.f : (1.f / dd);
    float4 ed;
    ed.x = col_pos[(size_t)c * 3 + 0];
    ed.y = col_pos[(size_t)c * 3 + 1];
    ed.z = col_pos[(size_t)c * 3 + 2];
    ed.w = inv;
    g_edata[e] = ed;
}

// ---------------- fused TF32 tensor-core GEMM (Q & K), 2-stage cp.async -----
// BM=BN=128, BK=32, 2-stage (73.7 KB smem -> 2 CTA/SM), 128 threads
// (4 warps, 2x2 grid), warp tile 64x64 -> 32 LDS / 32 MMA per k-step,
// mma.m16n8k8.tf32, pitch 36 (conflict-free: bank = 4g+t mod 32).
#define GBM 128
#define GBN 128
#define GBK 32
#define KPITCH 36
#define STAGE_FLOATS ((GBM + GBN) * KPITCH)          // 9216
#define GEMM_SMEM_BYTES (2 * STAGE_FLOATS * 4)        // 73728

__device__ __forceinline__ void cp_async16(uint32_t smem_addr, const void* gptr) {
    asm volatile("cp.async.cg.shared.global [%0], [%1], 16;\n"
                 :: "r"(smem_addr), "l"(gptr));
}
__device__ __forceinline__ void cp_commit() {
    asm volatile("cp.async.commit_group;\n");
}
__device__ __forceinline__ void cp_wait1() {
    asm volatile("cp.async.wait_group 1;\n");
}

__global__ __launch_bounds__(128, 2)
void gemm_tf32_fused(const float* __restrict__ A,
                     const float* __restrict__ Wq, const float* __restrict__ bq,
                     const float* __restrict__ Wk, const float* __restrict__ bk,
                     float* __restrict__ Cq, float* __restrict__ Ck)
{
    extern __shared__ float smem[];

    const int z = blockIdx.z;
    const float* W    = z ? Wk : Wq;
    const float* bias = z ? bk : bq;
    float*       C    = z ? Ck : Cq;
    const float scale = z ? 1.0f : 0.125f;   // q gets 1/sqrt(64)

    const int tid  = threadIdx.x;
    const int bm   = blockIdx.y;
    const int bn   = blockIdx.x;
    const int wid  = tid >> 5;
    const int lane = tid & 31;
    const int warp_m = wid >> 1;     // 0..1 -> 64 rows each
    const int warp_n = wid & 1;      // 0..1 -> 64 cols each
    const int g = lane >> 2;         // 0..7
    const int t = lane & 3;          // 0..3

    // global->smem: 8 A chunks + 8 B chunks (16B each) per thread per stage
    const int rA = tid >> 3;         // base row 0..15 (rows rA + 16*j)
    const int kc = (tid & 7) * 4;    // 0..28

    const float* Ag = A + (size_t)(bm * GBM + rA) * E_DIM + kc;
    const float* Wg = W + (size_t)(bn * GBN + rA) * E_DIM + kc;

    const uint32_t sbase = (uint32_t)__cvta_generic_to_shared(smem);
    const uint32_t aoff = (rA * KPITCH + kc) * 4;
    const uint32_t boff = (GBM * KPITCH + rA * KPITCH + kc) * 4;

    float acc[4][8][4];
    #pragma unroll
    for (int i = 0; i < 4; i++)
        #pragma unroll
        for (int j = 0; j < 8; j++)
            #pragma unroll
            for (int c = 0; c < 4; c++) acc[i][j][c] = 0.f;

    // prologue: stage 0
    {
        const uint32_t sb = sbase;
        #pragma unroll
        for (int j = 0; j < 8; j++) {
            cp_async16(sb + aoff + j * (16 * KPITCH * 4), Ag + (size_t)j * 16 * E_DIM);
            cp_async16(sb + boff + j * (16 * KPITCH * 4), Wg + (size_t)j * 16 * E_DIM);
        }
    }
    cp_commit();

    const int NIT = E_DIM / GBK;     // 16
    int cur = 0;

    for (int it = 0; it < NIT; it++) {
        if (it + 1 < NIT) {
            const int koff = (it + 1) * GBK;
            const uint32_t sb = sbase + (uint32_t)(cur ^ 1) * (STAGE_FLOATS * 4);
            #pragma unroll
            for (int j = 0; j < 8; j++) {
                cp_async16(sb + aoff + j * (16 * KPITCH * 4),
                           Ag + koff + (size_t)j * 16 * E_DIM);
                cp_async16(sb + boff + j * (16 * KPITCH * 4),
                           Wg + koff + (size_t)j * 16 * E_DIM);
            }
        }
        cp_commit();
        cp_wait1();
        __syncthreads();

        const float* __restrict__ Ac = smem + cur * STAGE_FLOATS;
        const float* __restrict__ Bc = Ac + GBM * KPITCH;

        #pragma unroll
        for (int ks = 0; ks < 4; ks++) {
            const int kb = ks * 8;
            uint32_t af[4][4], bf[8][2];
            #pragma unroll
            for (int i = 0; i < 4; i++) {
                int m = warp_m * 64 + i * 16;
                af[i][0] = __float_as_uint(Ac[(m + g    ) * KPITCH + kb + t    ]);
                af[i][1] = __float_as_uint(Ac[(m + g + 8) * KPITCH + kb + t    ]);
                af[i][2] = __float_as_uint(Ac[(m + g    ) * KPITCH + kb + t + 4]);
                af[i][3] = __float_as_uint(Ac[(m + g + 8) * KPITCH + kb + t + 4]);
            }
            #pragma unroll
            for (int j = 0; j < 8; j++) {
                int n = warp_n * 64 + j * 8;
                bf[j][0] = __float_as_uint(Bc[(n + g) * KPITCH + kb + t    ]);
                bf[j][1] = __float_as_uint(Bc[(n + g) * KPITCH + kb + t + 4]);
            }
            #pragma unroll
            for (int i = 0; i < 4; i++)
                #pragma unroll
                for (int j = 0; j < 8; j++) {
                    asm volatile(
                        "mma.sync.aligned.m16n8k8.row.col.f32.tf32.tf32.f32 "
                        "{%0,%1,%2,%3}, {%4,%5,%6,%7}, {%8,%9}, {%0,%1,%2,%3};"
                        : "+f"(acc[i][j][0]), "+f"(acc[i][j][1]),
                          "+f"(acc[i][j][2]), "+f"(acc[i][j][3])
                        : "r"(af[i][0]), "r"(af[i][1]), "r"(af[i][2]), "r"(af[i][3]),
                          "r"(bf[j][0]), "r"(bf[j][1]));
                }
        }
        __syncthreads();
        cur ^= 1;
    }

    const int mbase = bm * GBM + warp_m * 64;
    const int nbase = bn * GBN + warp_n * 64;
    #pragma unroll
    for (int i = 0; i < 4; i++) {
        #pragma unroll
        for (int j = 0; j < 8; j++) {
            int row0e = mbase + i * 16 + g;
            int col   = nbase + j * 8 + t * 2;
            float b0 = bias[col], b1 = bias[col + 1];
            float2 o0, o1;
            o0.x = (acc[i][j][0] + b0) * scale;
            o0.y = (acc[i][j][1] + b1) * scale;
            o1.x = (acc[i][j][2] + b0) * scale;
            o1.y = (acc[i][j][3] + b1) * scale;
            *(float2*)(C + (size_t)row0e * E_DIM + col)       = o0;
            *(float2*)(C + (size_t)(row0e + 8) * E_DIM + col) = o1;
        }
    }
}

// ---------------- fused edge logits + softmax + output ----------------------
// One warp per row; lane l holds Q floats [l*16,l*16+16); 2 edges/iteration;
// no max-subtraction (shift-invariant softmax, small logits). Per-edge data
// from precomputed g_edata/g_tcol.
__global__ __launch_bounds__(256)
void fused_attn_kernel(const float* __restrict__ pos,
                       float* __restrict__ out)
{
    int r = (blockIdx.x * blockDim.x + threadIdx.x) >> 5;
    if (r >= N_NODES) return;
    const int lane = threadIdx.x & 31;

    const int s  = g_rowptr[r];
    const int e1 = g_rowptr[r + 1];

    if (s == e1) {
        if (lane < H_HEADS)
            *(float4*)(out + (size_t)r * (H_HEADS * 4) + lane * 4) =
                make_float4(0.f, 0.f, 0.f, 0.f);
        return;
    }

    float4 q0, q1, q2, q3;
    {
        const float4* qp = (const float4*)(g_Q + (size_t)r * E_DIM + lane * 16);
        q0 = qp[0]; q1 = qp[1]; q2 = qp[2]; q3 = qp[3];
    }

    // two independent state sets (valid on lanes 0..7, head == lane)
    float zA = 0.f, sA = 0.f, vxA = 0.f, vyA = 0.f, vzA = 0.f;
    float zB = 0.f, sB = 0.f, vxB = 0.f, vyB = 0.f, vzB = 0.f;
    const int bsrc = (lane * 4) & 31;   // shfl source for head==lane

    for (int base = s; base < e1; base += 32) {
        int myE = base + lane;
        int tc = (myE < e1) ? g_tcol[myE] : 0;
        int cnt = min(32, e1 - base);

        int i = 0;
        for (; i + 2 <= cnt; i += 2) {
            int t0 = __shfl_sync(0xFFFFFFFFu, tc, i);
            int t1 = __shfl_sync(0xFFFFFFFFu, tc, i + 1);
            const float4* kpa = (const float4*)(g_K + (size_t)t0 * E_DIM + lane * 16);
            const float4* kpb = (const float4*)(g_K + (size_t)t1 * E_DIM + lane * 16);
            float4 a0 = kpa[0], a1 = kpa[1], a2 = kpa[2], a3 = kpa[3];
            float4 b0 = kpb[0], b1 = kpb[1], b2 = kpb[2], b3 = kpb[3];

            float d0 = q0.x * a0.x, d1 = q0.x * b0.x;
            d0 = fmaf(q0.y, a0.y, d0); d1 = fmaf(q0.y, b0.y, d1);
            d0 = fmaf(q0.z, a0.z, d0); d1 = fmaf(q0.z, b0.z, d1);
            d0 = fmaf(q0.w, a0.w, d0); d1 = fmaf(q0.w, b0.w, d1);
            d0 = fmaf(q1.x, a1.x, d0); d1 = fmaf(q1.x, b1.x, d1);
            d0 = fmaf(q1.y, a1.y, d0); d1 = fmaf(q1.y, b1.y, d1);
            d0 = fmaf(q1.z, a1.z, d0); d1 = fmaf(q1.z, b1.z, d1);
            d0 = fmaf(q1.w, a1.w, d0); d1 = fmaf(q1.w, b1.w, d1);
            d0 = fmaf(q2.x, a2.x, d0); d1 = fmaf(q2.x, b2.x, d1);
            d0 = fmaf(q2.y, a2.y, d0); d1 = fmaf(q2.y, b2.y, d1);
            d0 = fmaf(q2.z, a2.z, d0); d1 = fmaf(q2.z, b2.z, d1);
            d0 = fmaf(q2.w, a2.w, d0); d1 = fmaf(q2.w, b2.w, d1);
            d0 = fmaf(q3.x, a3.x, d0); d1 = fmaf(q3.x, b3.x, d1);
            d0 = fmaf(q3.y, a3.y, d0); d1 = fmaf(q3.y, b3.y, d1);
            d0 = fmaf(q3.z, a3.z, d0); d1 = fmaf(q3.z, b3.z, d1);
            d0 = fmaf(q3.w, a3.w, d0); d1 = fmaf(q3.w, b3.w, d1);

            d0 += __shfl_xor_sync(0xFFFFFFFFu, d0, 1);
            d1 += __shfl_xor_sync(0xFFFFFFFFu, d1, 1);
            d0 += __shfl_xor_sync(0xFFFFFFFFu, d0, 2);
            d1 += __shfl_xor_sync(0xFFFFFFFFu, d1, 2);

            float hv0 = __shfl_sync(0xFFFFFFFFu, d0, bsrc);
            float hv1 = __shfl_sync(0xFFFFFFFFu, d1, bsrc);

            if (lane < H_HEADS) {
                float4 ed0 = g_edata[base + i];
                float4 ed1 = g_edata[base + i + 1];
                float lg0 = hv0 + g_biasT[(size_t)(base + i)     * H_HEADS + lane];
                float lg1 = hv1 + g_biasT[(size_t)(base + i + 1) * H_HEADS + lane];
                float p0 = __expf(lg0), p1 = __expf(lg1);
                float w0 = p0 * ed0.w, w1 = p1 * ed1.w;
                zA += p0;  zB += p1;
                sA += w0;  sB += w1;
                vxA = fmaf(w0, ed0.x, vxA);  vxB = fmaf(w1, ed1.x, vxB);
                vyA = fmaf(w0, ed0.y, vyA);  vyB = fmaf(w1, ed1.y, vyB);
                vzA = fmaf(w0, ed0.z, vzA);  vzB = fmaf(w1, ed1.z, vzB);
            }
        }
        if (i < cnt) {
            int t0 = __shfl_sync(0xFFFFFFFFu, tc, i);
            const float4* kpa = (const float4*)(g_K + (size_t)t0 * E_DIM + lane * 16);
            float4 a0 = kpa[0], a1 = kpa[1], a2 = kpa[2], a3 = kpa[3];
            float d0 = q0.x * a0.x;
            d0 = fmaf(q0.y, a0.y, d0); d0 = fmaf(q0.z, a0.z, d0); d0 = fmaf(q0.w, a0.w, d0);
            d0 = fmaf(q1.x, a1.x, d0); d0 = fmaf(q1.y, a1.y, d0);
            d0 = fmaf(q1.z, a1.z, d0); d0 = fmaf(q1.w, a1.w, d0);
            d0 = fmaf(q2.x, a2.x, d0); d0 = fmaf(q2.y, a2.y, d0);
            d0 = fmaf(q2.z, a2.z, d0); d0 = fmaf(q2.w, a2.w, d0);
            d0 = fmaf(q3.x, a3.x, d0); d0 = fmaf(q3.y, a3.y, d0);
            d0 = fmaf(q3.z, a3.z, d0); d0 = fmaf(q3.w, a3.w, d0);
            d0 += __shfl_xor_sync(0xFFFFFFFFu, d0, 1);
            d0 += __shfl_xor_sync(0xFFFFFFFFu, d0, 2);
            float hv0 = __shfl_sync(0xFFFFFFFFu, d0, bsrc);
            if (lane < H_HEADS) {
                float4 ed0 = g_edata[base + i];
                float lg0 = hv0 + g_biasT[(size_t)(base + i) * H_HEADS + lane];
                float p0 = __expf(lg0);
                float w0 = p0 * ed0.w;
                zA += p0; sA += w0;
                vxA = fmaf(w0, ed0.x, vxA);
                vyA = fmaf(w0, ed0.y, vyA);
                vzA = fmaf(w0, ed0.z, vzA);
            }
        }
    }

    if (lane < H_HEADS) {
        float z  = zA + zB;
        float s0 = sA + sB;
        float vx = vxA + vxB, vy = vyA + vyB, vz = vzA + vzB;
        float4 o = make_float4(0.f, 0.f, 0.f, 0.f);
        if (z > 0.f) {
            float invZ = 1.f / z;
            float avg = s0 * invZ;
            float px = pos[(size_t)r * 3 + 0];
            float py = pos[(size_t)r * 3 + 1];
            float pz = pos[(size_t)r * 3 + 2];
            float dx = vx * invZ - avg * px;
            float dy = vy * invZ - avg * py;
            float dz = vz * invZ - avg * pz;
            float nm = sqrtf(dx * dx + dy * dy + dz * dz);
            float dnm = fmaxf(nm, 1e-12f);
            o.x = dx / dnm; o.y = dy / dnm; o.z = dz / dnm; o.w = avg;
        }
        *(float4*)(out + (size_t)r * (H_HEADS * 4) + lane * 4) = o;
    }
}

// ---------------- launch ----------------------------------------------------
extern "C" void kernel_launch(void* const* d_in, const int* in_sizes, int n_in,
                              void* d_out, int out_size)
{
    const float* x            = (const float*)d_in[0];
    const int*   row_index    = (const int*)  d_in[1];
    const int*   col_index    = (const int*)  d_in[2];
    const int*   to_col_index = (const int*)  d_in[3];
    const float* att_bias     = (const float*)d_in[4];
    const float* dist         = (const float*)d_in[5];
    const float* pos          = (const float*)d_in[6];
    const float* col_pos      = (const float*)d_in[7];
    const float* q_w          = (const float*)d_in[8];
    const float* q_b          = (const float*)d_in[9];
    const float* k_w          = (const float*)d_in[10];
    const float* k_b          = (const float*)d_in[11];
    float* out = (float*)d_out;

    float* Qg; cudaGetSymbolAddress((void**)&Qg, g_Q);
    float* Kg; cudaGetSymbolAddress((void**)&Kg, g_K);

    prep_kernel<<<NNZ_E / 256, 256>>>(row_index, att_bias, col_index,
                                      to_col_index, dist, col_pos);

    cudaFuncSetAttribute(gemm_tf32_fused,
                         cudaFuncAttributeMaxDynamicSharedMemorySize,
                         GEMM_SMEM_BYTES);
    dim3 ggrid(E_DIM / GBN, N_NODES / GBM, 2);
    gemm_tf32_fused<<<ggrid, 128, GEMM_SMEM_BYTES>>>(x, q_w, q_b, k_w, k_b, Qg, Kg);

    fused_attn_kernel<<<N_NODES / 8, 256>>>(pos, out);
}